// round 9
// baseline (speedup 1.0000x reference)
#include <cuda_runtime.h>
#include <cuda_bf16.h>
#include <cuda_fp16.h>
#include <cstdint>
#include <cstddef>

#define NNODE 50000
#define NEDGE 800000
#define NTOT  850000   // edges + self loops
#define HEADS 8
#define NB_SCAN 98     // ceil(NNODE/512)

// ---------------- scratch (device globals; no allocations allowed) -------------
__device__ uint8_t g_h0f8[(size_t)NNODE * 512];       // layer0 features e4m3 [N][8][64]
__device__ __nv_bfloat16 g_h2b[(size_t)NNODE * 320];  // layer2 features bf16 [N][8][40]
__device__ __nv_bfloat16 g_xb[(size_t)NNODE * 256];   // input x in bf16
__device__ __nv_bfloat16 g_hmidb[(size_t)NNODE * 64]; // relu(mean-head layer0) bf16
__device__ __nv_bfloat16 g_w0b[512 * 256];            // W0 bf16
__device__ __nv_bfloat16 g_w2b[320 * 64];             // W2 bf16
__device__ float g_as0[NNODE * 8], g_ad0[NNODE * 8];
__device__ float g_as2[NNODE * 8], g_ad2[NNODE * 8];
__device__ float g_va0[16 * 256];                     // folded attention vecs (fp32 exact)
__device__ float g_va2[16 * 64];
__device__ int   g_cnt[NNODE];
__device__ int   g_rs[NNODE + 1];                     // CSR row_start by dst
__device__ int   g_cur[NNODE];
__device__ int   g_bsum[NB_SCAN];
__device__ int   g_csrc[NTOT];                        // CSR src indices
__device__ int   g_shift;                             // 1 if edge_index is int64, 0 if int32
__device__ int   g_ctr0, g_ctr2;                      // persistent work counters

// ---------------- small helpers -------------
__device__ __forceinline__ uint32_t smem_u32(const void* p) {
    return (uint32_t)__cvta_generic_to_shared(p);
}
__device__ __forceinline__ void cp_async16(uint32_t saddr, const void* gptr, bool pred) {
    int sz = pred ? 16 : 0;
    asm volatile("cp.async.cg.shared.global [%0], [%1], 16, %2;\n"
                 :: "r"(saddr), "l"(gptr), "r"(sz));
}
__device__ __forceinline__ void ldsm4(uint32_t& r0, uint32_t& r1, uint32_t& r2, uint32_t& r3, uint32_t a) {
    asm volatile("ldmatrix.sync.aligned.m8n8.x4.shared.b16 {%0,%1,%2,%3}, [%4];\n"
                 : "=r"(r0), "=r"(r1), "=r"(r2), "=r"(r3) : "r"(a));
}
__device__ __forceinline__ void mma_bf16(float* c, uint32_t a0, uint32_t a1, uint32_t a2, uint32_t a3,
                                         uint32_t b0, uint32_t b1) {
    asm volatile(
        "mma.sync.aligned.m16n8k16.row.col.f32.bf16.bf16.f32 "
        "{%0,%1,%2,%3},{%4,%5,%6,%7},{%8,%9},{%0,%1,%2,%3};\n"
        : "+f"(c[0]), "+f"(c[1]), "+f"(c[2]), "+f"(c[3])
        : "r"(a0), "r"(a1), "r"(a2), "r"(a3), "r"(b0), "r"(b1));
}
__device__ __forceinline__ uint16_t pack_e4m3(float lo, float hi) {
    uint16_t r;
    asm("cvt.rn.satfinite.e4m3x2.f32 %0, %1, %2;" : "=h"(r) : "f"(hi), "f"(lo));
    return r;
}
__device__ __forceinline__ float2 unpack_e4m3(uint32_t u16) {
    uint32_t h2;
    asm("cvt.rn.f16x2.e4m3x2 %0, %1;" : "=r"(h2) : "h"((uint16_t)u16));
    return __half22float2(*reinterpret_cast<__half2*>(&h2));
}

// ---------------- prep (main stream): va vectors + weight bf16 conversion ----------------
__global__ void prep_main_kernel(const float* __restrict__ W0, const float* __restrict__ a0s,
                                 const float* __restrict__ a0d,
                                 const float* __restrict__ W2, const float* __restrict__ a2s,
                                 const float* __restrict__ a2d) {
    int b = blockIdx.x, t = threadIdx.x;
    if (b == 0) {
#pragma unroll 1
        for (int v = 0; v < 16; v++) {
            int h = v & 7;
            const float* att = (v < 8) ? a0s : a0d;
            float acc = 0.f;
            for (int c = 0; c < 64; c++)
                acc = fmaf(att[h * 64 + c], W0[(size_t)(h * 64 + c) * 256 + t], acc);
            g_va0[v * 256 + t] = acc;
        }
    } else if (b == 1) {
        if (t < 64) {
#pragma unroll 1
            for (int v = 0; v < 16; v++) {
                int h = v & 7;
                const float* att = (v < 8) ? a2s : a2d;
                float acc = 0.f;
                for (int c = 0; c < 40; c++)
                    acc = fmaf(att[h * 40 + c], W2[(size_t)(h * 40 + c) * 64 + t], acc);
                g_va2[v * 64 + t] = acc;
            }
        }
    } else if (b < 514) {
        int i = (b - 2) * 256 + t;   // 512*256 = 131072
        g_w0b[i] = __float2bfloat16(W0[i]);
    } else {
        int i = (b - 514) * 256 + t; // 320*64 = 20480
        if (i < 320 * 64) g_w2b[i] = __float2bfloat16(W2[i]);
    }
}

// ---------------- prep (side stream): zero counters + dtype detect ----------------
__global__ void prep_csr_kernel(const int* __restrict__ ei) {
    int b = blockIdx.x, t = threadIdx.x;
    if (b < 196) {
        int i = b * 256 + t;
        if (i < NNODE) g_cnt[i] = 0;
    } else {
        __shared__ int s;
        if (t == 0) s = 0;
        if (t == 1) g_ctr0 = 0;
        if (t == 2) g_ctr2 = 0;
        __syncthreads();
        int v = ei[2 * t + 1];  // high words if int64 (always 0), random values if int32
        if (v != 0) atomicOr(&s, 1);
        __syncthreads();
        if (t == 0) g_shift = s ? 0 : 1;
    }
}

// ---------------- CSR build -------------
__global__ void count_kernel(const int* __restrict__ p) {
    int e = blockIdx.x * blockDim.x + threadIdx.x;
    if (e >= NTOT) return;
    int sh = g_shift;
    int dst = (e < NEDGE) ? p[(size_t)(NEDGE + e) << sh] : (e - NEDGE);
    atomicAdd(&g_cnt[dst], 1);
}
__global__ void scan1_kernel() {
    int i = blockIdx.x * 512 + threadIdx.x;
    int v = (i < NNODE) ? g_cnt[i] : 0;
    int lane = threadIdx.x & 31, w = threadIdx.x >> 5;
#pragma unroll
    for (int o = 16; o > 0; o >>= 1) v += __shfl_down_sync(0xffffffffu, v, o);
    __shared__ int ws[16];
    if (lane == 0) ws[w] = v;
    __syncthreads();
    if (w == 0) {
        int s = (lane < 16) ? ws[lane] : 0;
#pragma unroll
        for (int o = 8; o > 0; o >>= 1) s += __shfl_down_sync(0xffffffffu, s, o);
        if (lane == 0) g_bsum[blockIdx.x] = s;
    }
}
__global__ void scan2_kernel() {
    int t = threadIdx.x, lane = t & 31, w = t >> 5;
    int v = (t < NB_SCAN) ? g_bsum[t] : 0;
    int s = v;
#pragma unroll
    for (int o = 1; o < 32; o <<= 1) {
        int u = __shfl_up_sync(0xffffffffu, s, o);
        if (lane >= o) s += u;
    }
    __shared__ int wt[4];
    if (lane == 31) wt[w] = s;
    __syncthreads();
    int add = 0;
#pragma unroll
    for (int k = 0; k < 4; k++) if (k < w) add += wt[k];
    if (t < NB_SCAN) g_bsum[t] = s - v + add;
    if (t == 0) g_rs[NNODE] = wt[0] + wt[1] + wt[2] + wt[3];
}
__global__ void scan3_kernel() {
    int i = blockIdx.x * 512 + threadIdx.x;
    int t = threadIdx.x, lane = t & 31, w = t >> 5;
    int v = (i < NNODE) ? g_cnt[i] : 0;
    int s = v;
#pragma unroll
    for (int o = 1; o < 32; o <<= 1) {
        int u = __shfl_up_sync(0xffffffffu, s, o);
        if (lane >= o) s += u;
    }
    __shared__ int wt[16];
    if (lane == 31) wt[w] = s;
    __syncthreads();
    int add = g_bsum[blockIdx.x];
#pragma unroll
    for (int k = 0; k < 16; k++) if (k < w) add += wt[k];
    if (i < NNODE) {
        int e = s - v + add;
        g_rs[i] = e;
        g_cur[i] = e;
    }
}
__global__ void fill_kernel(const int* __restrict__ p) {
    int e = blockIdx.x * blockDim.x + threadIdx.x;
    if (e >= NTOT) return;
    int sh = g_shift;
    int src, dst;
    if (e < NEDGE) {
        src = p[(size_t)e << sh];
        dst = p[(size_t)(NEDGE + e) << sh];
    } else {
        src = dst = e - NEDGE;
    }
    int pos = atomicAdd(&g_cur[dst], 1);
    g_csrc[pos] = src;
}

// ---------------- node logits from x (fp32 exact) + fused x->bf16 conversion -------------
__global__ void logits0_kernel(const float* __restrict__ x) {
    __shared__ float sx[16][256];
    __shared__ float sv[16][257];
    int t = threadIdx.x;
    int nb = blockIdx.x * 16;
    for (int i = t; i < 4096; i += 256) {
        int r = i >> 8, c = i & 255;
        sv[r][c] = g_va0[i];
        int n = nb + r;
        float v = (n < NNODE) ? x[(size_t)n * 256 + c] : 0.f;
        sx[r][c] = v;
        if (n < NNODE) g_xb[(size_t)n * 256 + c] = __float2bfloat16(v);
    }
    __syncthreads();
    int ni = t >> 4, vi = t & 15;
    float acc = 0.f;
#pragma unroll 8
    for (int j = 0; j < 256; j++) acc = fmaf(sx[ni][j], sv[vi][j], acc);
    int n = nb + ni;
    if (n < NNODE) {
        if (vi < 8) g_as0[n * 8 + vi] = acc;
        else        g_ad0[n * 8 + vi - 8] = acc;
    }
}

// ---------------- bf16 tensor-core GEMM: C[M,Nc] = A[M,K] * B[Nc,K]^T ----------
template <int LAYER>
__global__ void __launch_bounds__(256, 2)
gemm_bf16_nt(int M, int Nc, int K) {
    extern __shared__ char smem[];
    const __nv_bfloat16* A  = (LAYER == 0) ? g_xb : g_hmidb;
    const __nv_bfloat16* Bw = (LAYER == 0) ? g_w0b : g_w2b;

    int tid = threadIdx.x, lane = tid & 31, w = tid >> 5;
    int bm = blockIdx.x * 128, bn = blockIdx.y * 128;
    int wm = (w & 3) * 32, wn = (w >> 2) * 64;

    float c[2][8][4];
#pragma unroll
    for (int mt = 0; mt < 2; mt++)
#pragma unroll
        for (int nt = 0; nt < 8; nt++)
#pragma unroll
            for (int j = 0; j < 4; j++) c[mt][nt][j] = 0.f;

    uint32_t sbase = smem_u32(smem);

    auto issue = [&](int s, int k0) {   // k0 in elements
#pragma unroll
        for (int i = 0; i < 4; i++) {
            int c0 = tid + i * 256;
            int row = c0 >> 3, ch = c0 & 7;
            uint32_t off = (uint32_t)(row * 128 + ch * 16) ^ (uint32_t)((row & 7) << 4);
            cp_async16(sbase + s * 16384 + off, A + (size_t)(bm + row) * K + k0 + ch * 8, bm + row < M);
            cp_async16(sbase + 32768 + s * 16384 + off, Bw + (size_t)(bn + row) * K + k0 + ch * 8, bn + row < Nc);
        }
        asm volatile("cp.async.commit_group;\n");
    };

    int a_row = (lane & 15);
    int a_cb = (lane >> 4) << 4;
    int b_row = ((lane >> 4) & 1) * 8 + (lane & 7);
    int b_cb = ((lane >> 3) & 1) << 4;

    int T = K >> 6;
    issue(0, 0);
    for (int t = 0; t < T; t++) {
        if (t + 1 < T) {
            issue((t + 1) & 1, (t + 1) << 6);
            asm volatile("cp.async.wait_group 1;\n");
        } else {
            asm volatile("cp.async.wait_group 0;\n");
        }
        __syncthreads();
        uint32_t aB = sbase + (t & 1) * 16384;
        uint32_t bB = sbase + 32768 + (t & 1) * 16384;
#pragma unroll
        for (int ks = 0; ks < 4; ks++) {
            uint32_t a[2][4], b[4][4];
#pragma unroll
            for (int mt = 0; mt < 2; mt++) {
                int row = wm + mt * 16 + a_row;
                uint32_t off = (uint32_t)(row * 128 + ks * 32 + a_cb) ^ (uint32_t)((row & 7) << 4);
                ldsm4(a[mt][0], a[mt][1], a[mt][2], a[mt][3], aB + off);
            }
#pragma unroll
            for (int pt = 0; pt < 4; pt++) {
                int row = wn + pt * 16 + b_row;
                uint32_t off = (uint32_t)(row * 128 + ks * 32 + b_cb) ^ (uint32_t)((row & 7) << 4);
                ldsm4(b[pt][0], b[pt][1], b[pt][2], b[pt][3], bB + off);
            }
#pragma unroll
            for (int mt = 0; mt < 2; mt++)
#pragma unroll
                for (int nt = 0; nt < 8; nt++) {
                    int pt = nt >> 1;
                    mma_bf16(c[mt][nt], a[mt][0], a[mt][1], a[mt][2], a[mt][3],
                             b[pt][(nt & 1) * 2], b[pt][(nt & 1) * 2 + 1]);
                }
        }
        __syncthreads();
    }
    int gr0 = bm + wm + (lane >> 2);
    int gc0 = bn + wn + (lane & 3) * 2;
#pragma unroll
    for (int mt = 0; mt < 2; mt++) {
#pragma unroll
        for (int nt = 0; nt < 8; nt++) {
            int col = gc0 + nt * 8;
            if (col < Nc) {
                int r0 = gr0 + mt * 16;
                int r1 = r0 + 8;
                if (LAYER == 0) {
                    if (r0 < M) *(uint16_t*)&g_h0f8[(size_t)r0 * Nc + col] = pack_e4m3(c[mt][nt][0], c[mt][nt][1]);
                    if (r1 < M) *(uint16_t*)&g_h0f8[(size_t)r1 * Nc + col] = pack_e4m3(c[mt][nt][2], c[mt][nt][3]);
                } else {
                    if (r0 < M) {
                        __nv_bfloat162 v = __float22bfloat162_rn(make_float2(c[mt][nt][0], c[mt][nt][1]));
                        *(__nv_bfloat162*)&g_h2b[(size_t)r0 * Nc + col] = v;
                    }
                    if (r1 < M) {
                        __nv_bfloat162 v = __float22bfloat162_rn(make_float2(c[mt][nt][2], c[mt][nt][3]));
                        *(__nv_bfloat162*)&g_h2b[(size_t)r1 * Nc + col] = v;
                    }
                }
            }
        }
    }
}

// ---------------- layer0 pull: persistent warps, 4x unroll, fused logits2 ----------------
__global__ void __launch_bounds__(256) pull0_kernel(const float* __restrict__ b0) {
    __shared__ float sva[16 * 64];
    __shared__ float sb0[64];
    int t = threadIdx.x, lane = t & 31;
    for (int i = t; i < 1024; i += 256) sva[i] = g_va2[i];
    if (t < 64) sb0[t] = b0[t];
    __syncthreads();
    int head = lane >> 2, colg = lane & 3;
    for (;;) {
        int gw;
        if (lane == 0) gw = atomicAdd(&g_ctr0, 1);
        gw = __shfl_sync(0xffffffffu, gw, 0);
        if (gw >= NNODE) break;

        float sd = g_ad0[gw * 8 + head];
        int beg = g_rs[gw], end = g_rs[gw + 1];
        float acc[16];
#pragma unroll
        for (int j = 0; j < 16; j++) acc[j] = 0.f;
        float wsum = 0.f;

        int i = beg;
        for (; i < end && (i & 3); i++) {
            int s0 = g_csrc[i];
            float el = g_as0[s0 * 8 + head] + sd;
            el = el > 0.f ? el : 0.2f * el;
            float w0 = __expf(el);
            wsum += w0;
            uint4 ua = *(const uint4*)(g_h0f8 + (size_t)s0 * 512 + lane * 16);
            const uint32_t va[4] = {ua.x, ua.y, ua.z, ua.w};
#pragma unroll
            for (int q = 0; q < 4; q++) {
                float2 a0 = unpack_e4m3(va[q] & 0xffffu);
                float2 a1 = unpack_e4m3(va[q] >> 16);
                acc[q * 4 + 0] = fmaf(w0, a0.x, acc[q * 4 + 0]);
                acc[q * 4 + 1] = fmaf(w0, a0.y, acc[q * 4 + 1]);
                acc[q * 4 + 2] = fmaf(w0, a1.x, acc[q * 4 + 2]);
                acc[q * 4 + 3] = fmaf(w0, a1.y, acc[q * 4 + 3]);
            }
        }
        for (; i + 4 <= end; i += 4) {
            int4 s4 = *(const int4*)(g_csrc + i);
            float l0 = g_as0[s4.x * 8 + head], l1 = g_as0[s4.y * 8 + head];
            float l2 = g_as0[s4.z * 8 + head], l3 = g_as0[s4.w * 8 + head];
            uint4 u0 = *(const uint4*)(g_h0f8 + (size_t)s4.x * 512 + lane * 16);
            uint4 u1 = *(const uint4*)(g_h0f8 + (size_t)s4.y * 512 + lane * 16);
            uint4 u2 = *(const uint4*)(g_h0f8 + (size_t)s4.z * 512 + lane * 16);
            uint4 u3 = *(const uint4*)(g_h0f8 + (size_t)s4.w * 512 + lane * 16);
            float e0 = l0 + sd; e0 = e0 > 0.f ? e0 : 0.2f * e0;
            float e1 = l1 + sd; e1 = e1 > 0.f ? e1 : 0.2f * e1;
            float e2 = l2 + sd; e2 = e2 > 0.f ? e2 : 0.2f * e2;
            float e3 = l3 + sd; e3 = e3 > 0.f ? e3 : 0.2f * e3;
            float w0 = __expf(e0), w1 = __expf(e1), w2 = __expf(e2), w3 = __expf(e3);
            wsum += (w0 + w1) + (w2 + w3);
            const uint32_t* p0 = &u0.x;
            const uint32_t* p1 = &u1.x;
            const uint32_t* p2 = &u2.x;
            const uint32_t* p3 = &u3.x;
#pragma unroll
            for (int q = 0; q < 4; q++) {
                float2 a0 = unpack_e4m3(p0[q] & 0xffffu), a1 = unpack_e4m3(p0[q] >> 16);
                float2 c0 = unpack_e4m3(p1[q] & 0xffffu), c1 = unpack_e4m3(p1[q] >> 16);
                float2 d0 = unpack_e4m3(p2[q] & 0xffffu), d1 = unpack_e4m3(p2[q] >> 16);
                float2 f0 = unpack_e4m3(p3[q] & 0xffffu), f1 = unpack_e4m3(p3[q] >> 16);
                acc[q * 4 + 0] = fmaf(w3, f0.x, fmaf(w2, d0.x, fmaf(w1, c0.x, fmaf(w0, a0.x, acc[q * 4 + 0]))));
                acc[q * 4 + 1] = fmaf(w3, f0.y, fmaf(w2, d0.y, fmaf(w1, c0.y, fmaf(w0, a0.y, acc[q * 4 + 1]))));
                acc[q * 4 + 2] = fmaf(w3, f1.x, fmaf(w2, d1.x, fmaf(w1, c1.x, fmaf(w0, a1.x, acc[q * 4 + 2]))));
                acc[q * 4 + 3] = fmaf(w3, f1.y, fmaf(w2, d1.y, fmaf(w1, c1.y, fmaf(w0, a1.y, acc[q * 4 + 3]))));
            }
        }
        for (; i < end; i++) {
            int s0 = g_csrc[i];
            float el = g_as0[s0 * 8 + head] + sd;
            el = el > 0.f ? el : 0.2f * el;
            float w0 = __expf(el);
            wsum += w0;
            uint4 ua = *(const uint4*)(g_h0f8 + (size_t)s0 * 512 + lane * 16);
            const uint32_t va[4] = {ua.x, ua.y, ua.z, ua.w};
#pragma unroll
            for (int q = 0; q < 4; q++) {
                float2 a0 = unpack_e4m3(va[q] & 0xffffu);
                float2 a1 = unpack_e4m3(va[q] >> 16);
                acc[q * 4 + 0] = fmaf(w0, a0.x, acc[q * 4 + 0]);
                acc[q * 4 + 1] = fmaf(w0, a0.y, acc[q * 4 + 1]);
                acc[q * 4 + 2] = fmaf(w0, a1.x, acc[q * 4 + 2]);
                acc[q * 4 + 3] = fmaf(w0, a1.y, acc[q * 4 + 3]);
            }
        }

        float inv = 1.f / (wsum + 1e-16f);
#pragma unroll
        for (int j = 0; j < 16; j++) acc[j] *= inv;
#pragma unroll
        for (int j = 0; j < 16; j++) {
            acc[j] += __shfl_xor_sync(0xffffffffu, acc[j], 4);
            acc[j] += __shfl_xor_sync(0xffffffffu, acc[j], 8);
            acc[j] += __shfl_xor_sync(0xffffffffu, acc[j], 16);
        }
        // all lanes now hold mean-head values for cols colg*16 + j
        float o[16];
#pragma unroll
        for (int j = 0; j < 16; j++) {
            float r = acc[j] * 0.125f + sb0[colg * 16 + j];
            o[j] = r > 0.f ? r : 0.f;
        }
        if (lane < 4) {
            __nv_bfloat162* op = (__nv_bfloat162*)(g_hmidb + (size_t)gw * 64 + lane * 16);
#pragma unroll
            for (int q = 0; q < 8; q++)
                op[q] = __float22bfloat162_rn(make_float2(o[q * 2], o[q * 2 + 1]));
        }
        // fused layer-2 logits: d_v = hmid . va2[v]  (fp32 exact)
#pragma unroll 1
        for (int v = 0; v < 16; v++) {
            float d = 0.f;
            const float* vp = &sva[v * 64 + colg * 16];
#pragma unroll
            for (int j = 0; j < 16; j++) d = fmaf(o[j], vp[j], d);
            d += __shfl_xor_sync(0xffffffffu, d, 1);
            d += __shfl_xor_sync(0xffffffffu, d, 2);
            if (lane == v) {
                if (v < 8) g_as2[gw * 8 + v] = d;
                else       g_ad2[gw * 8 + v - 8] = d;
            }
        }
    }
}

// ---------------- layer2 pull: persistent warps, 4x unroll, fused log_softmax ----------
__global__ void __launch_bounds__(256) pull2_kernel(const float* __restrict__ b2, float* __restrict__ out) {
    int t = threadIdx.x, lane = t & 31;
    int head = lane >> 2;
    for (;;) {
        int gw;
        if (lane == 0) gw = atomicAdd(&g_ctr2, 1);
        gw = __shfl_sync(0xffffffffu, gw, 0);
        if (gw >= NNODE) break;

        float sd = g_ad2[gw * 8 + head];
        int beg = g_rs[gw], end = g_rs[gw + 1];
        float acc[10];
#pragma unroll
        for (int j = 0; j < 10; j++) acc[j] = 0.f;
        float wsum = 0.f;

        int i = beg;
        for (; i < end && (i & 3); i++) {
            int s0 = g_csrc[i];
            float el = g_as2[s0 * 8 + head] + sd;
            el = el > 0.f ? el : 0.2f * el;
            float w0 = __expf(el);
            wsum += w0;
            const uint32_t* p0 = (const uint32_t*)(g_h2b + (size_t)s0 * 320 + lane * 10);
            uint32_t uu[5];
#pragma unroll
            for (int q = 0; q < 5; q++) uu[q] = p0[q];
#pragma unroll
            for (int q = 0; q < 5; q++) {
                float2 f = __bfloat1622float2(*(const __nv_bfloat162*)&uu[q]);
                acc[q * 2 + 0] = fmaf(w0, f.x, acc[q * 2 + 0]);
                acc[q * 2 + 1] = fmaf(w0, f.y, acc[q * 2 + 1]);
            }
        }
        for (; i + 4 <= end; i += 4) {
            int4 s4 = *(const int4*)(g_csrc + i);
            float l0 = g_as2[s4.x * 8 + head], l1 = g_as2[s4.y * 8 + head];
            float l2 = g_as2[s4.z * 8 + head], l3 = g_as2[s4.w * 8 + head];
            const uint32_t* p0 = (const uint32_t*)(g_h2b + (size_t)s4.x * 320 + lane * 10);
            const uint32_t* p1 = (const uint32_t*)(g_h2b + (size_t)s4.y * 320 + lane * 10);
            const uint32_t* p2 = (const uint32_t*)(g_h2b + (size_t)s4.z * 320 + lane * 10);
            const uint32_t* p3 = (const uint32_t*)(g_h2b + (size_t)s4.w * 320 + lane * 10);
            uint32_t ua[5], ub[5], uc[5], ud[5];
#pragma unroll
            for (int q = 0; q < 5; q++) { ua[q] = p0[q]; ub[q] = p1[q]; uc[q] = p2[q]; ud[q] = p3[q]; }
            float e0 = l0 + sd; e0 = e0 > 0.f ? e0 : 0.2f * e0;
            float e1 = l1 + sd; e1 = e1 > 0.f ? e1 : 0.2f * e1;
            float e2 = l2 + sd; e2 = e2 > 0.f ? e2 : 0.2f * e2;
            float e3 = l3 + sd; e3 = e3 > 0.f ? e3 : 0.2f * e3;
            float w0 = __expf(e0), w1 = __expf(e1), w2 = __expf(e2), w3 = __expf(e3);
            wsum += (w0 + w1) + (w2 + w3);
#pragma unroll
            for (int q = 0; q < 5; q++) {
                float2 f0 = __bfloat1622float2(*(const __nv_bfloat162*)&ua[q]);
                float2 f1 = __bfloat1622float2(*(const __nv_bfloat162*)&ub[q]);
                float2 f2 = __bfloat1622float2(*(const __nv_bfloat162*)&uc[q]);
                float2 f3 = __bfloat1622float2(*(const __nv_bfloat162*)&ud[q]);
                acc[q * 2 + 0] = fmaf(w3, f3.x, fmaf(w2, f2.x, fmaf(w1, f1.x, fmaf(w0, f0.x, acc[q * 2 + 0]))));
                acc[q * 2 + 1] = fmaf(w3, f3.y, fmaf(w2, f2.y, fmaf(w1, f1.y, fmaf(w0, f0.y, acc[q * 2 + 1]))));
            }
        }
        for (; i < end; i++) {
            int s0 = g_csrc[i];
            float el = g_as2[s0 * 8 + head] + sd;
            el = el > 0.f ? el : 0.2f * el;
            float w0 = __expf(el);
            wsum += w0;
            const uint32_t* p0 = (const uint32_t*)(g_h2b + (size_t)s0 * 320 + lane * 10);
            uint32_t uu[5];
#pragma unroll
            for (int q = 0; q < 5; q++) uu[q] = p0[q];
#pragma unroll
            for (int q = 0; q < 5; q++) {
                float2 f = __bfloat1622float2(*(const __nv_bfloat162*)&uu[q]);
                acc[q * 2 + 0] = fmaf(w0, f.x, acc[q * 2 + 0]);
                acc[q * 2 + 1] = fmaf(w0, f.y, acc[q * 2 + 1]);
            }
        }

        float inv = 1.f / (wsum + 1e-16f);
#pragma unroll
        for (int j = 0; j < 10; j++) acc[j] *= inv;
#pragma unroll
        for (int j = 0; j < 10; j++) {
            acc[j] += __shfl_xor_sync(0xffffffffu, acc[j], 4);
            acc[j] += __shfl_xor_sync(0xffffffffu, acc[j], 8);
            acc[j] += __shfl_xor_sync(0xffffffffu, acc[j], 16);
        }
        int co = (lane & 3) * 10;
        float val[10];
        float vmax = -1e30f;
#pragma unroll
        for (int j = 0; j < 10; j++) {
            val[j] = acc[j] * 0.125f + b2[co + j];
            vmax = fmaxf(vmax, val[j]);
        }
        vmax = fmaxf(vmax, __shfl_xor_sync(0xffffffffu, vmax, 1));
        vmax = fmaxf(vmax, __shfl_xor_sync(0xffffffffu, vmax, 2));
        float se = 0.f;
#pragma unroll
        for (int j = 0; j < 10; j++) se += __expf(val[j] - vmax);
        se += __shfl_xor_sync(0xffffffffu, se, 1);
        se += __shfl_xor_sync(0xffffffffu, se, 2);
        float lse = vmax + logf(se);
        if (lane < 4) {
            float* op = out + (size_t)gw * 40 + co;
#pragma unroll
            for (int q = 0; q < 5; q++)
                *(float2*)&op[q * 2] = make_float2(val[q * 2] - lse, val[q * 2 + 1] - lse);
        }
    }
}

// ---------------- launcher (forked-stream graph: CSR build || GEMM path) -----------------
extern "C" void kernel_launch(void* const* d_in, const int* in_sizes, int n_in,
                              void* d_out, int out_size) {
    const float* x   = (const float*)d_in[0];
    const int*   ei  = (const int*)d_in[1];
    // d_in[2] = edge_attr (unused by GATConv)
    const float* W0  = (const float*)d_in[3];
    const float* a0s = (const float*)d_in[4];
    const float* a0d = (const float*)d_in[5];
    const float* b0  = (const float*)d_in[6];
    const float* W2  = (const float*)d_in[7];
    const float* a2s = (const float*)d_in[8];
    const float* a2d = (const float*)d_in[9];
    const float* b2  = (const float*)d_in[10];
    float* out = (float*)d_out;

    static cudaStream_t s2 = nullptr;
    static cudaEvent_t evA = nullptr, evB = nullptr;
    if (!s2) {
        cudaStreamCreateWithFlags(&s2, cudaStreamNonBlocking);
        cudaEventCreateWithFlags(&evA, cudaEventDisableTiming);
        cudaEventCreateWithFlags(&evB, cudaEventDisableTiming);
        cudaFuncSetAttribute(gemm_bf16_nt<0>, cudaFuncAttributeMaxDynamicSharedMemorySize, 65536);
        cudaFuncSetAttribute(gemm_bf16_nt<1>, cudaFuncAttributeMaxDynamicSharedMemorySize, 65536);
    }

    // fork: CSR build chain on s2, compute chain on main stream
    cudaEventRecord(evA, 0);
    cudaStreamWaitEvent(s2, evA, 0);

    prep_csr_kernel<<<197, 256, 0, s2>>>(ei);
    count_kernel<<<(NTOT + 255) / 256, 256, 0, s2>>>(ei);
    scan1_kernel<<<NB_SCAN, 512, 0, s2>>>();
    scan2_kernel<<<1, 128, 0, s2>>>();
    scan3_kernel<<<NB_SCAN, 512, 0, s2>>>();
    fill_kernel<<<(NTOT + 255) / 256, 256, 0, s2>>>(ei);
    cudaEventRecord(evB, s2);

    prep_main_kernel<<<594, 256>>>(W0, a0s, a0d, W2, a2s, a2d);
    logits0_kernel<<<3125, 256>>>(x);
    gemm_bf16_nt<0><<<dim3(391, 4), 256, 65536>>>(NNODE, 512, 256);

    cudaStreamWaitEvent(0, evB, 0);
    pull0_kernel<<<444, 256>>>(b0);

    gemm_bf16_nt<1><<<dim3(391, 3), 256, 65536>>>(NNODE, 320, 64);
    pull2_kernel<<<444, 256>>>(b2, out);
}

// round 10
// speedup vs baseline: 1.0422x; 1.0422x over previous
#include <cuda_runtime.h>
#include <cuda_bf16.h>
#include <cuda_fp16.h>
#include <cstdint>
#include <cstddef>

#define NNODE 50000
#define NEDGE 800000
#define NTOT  850000   // edges + self loops
#define HEADS 8
#define NB_SCAN 98     // ceil(NNODE/512)

// ---------------- scratch (device globals; no allocations allowed) -------------
__device__ uint8_t g_h0f8[(size_t)NNODE * 512];       // layer0 features e4m3 [N][8][64]
__device__ __nv_bfloat16 g_h2b[(size_t)NNODE * 320];  // layer2 features bf16 [N][8][40]
__device__ __nv_bfloat16 g_xb[(size_t)NNODE * 256];   // input x in bf16
__device__ __nv_bfloat16 g_hmidb[(size_t)NNODE * 64]; // relu(mean-head layer0) bf16
__device__ __nv_bfloat16 g_w0b[512 * 256];            // W0 bf16
__device__ __nv_bfloat16 g_w2b[320 * 64];             // W2 bf16
__device__ float g_as0[NNODE * 8], g_ad0[NNODE * 8];
__device__ float g_as2[NNODE * 8], g_ad2[NNODE * 8];
__device__ float g_va0[16 * 256];                     // folded attention vecs (fp32 exact)
__device__ float g_va2[16 * 64];
__device__ int   g_cnt[NNODE];
__device__ int   g_rs[NNODE + 1];                     // CSR row_start by dst
__device__ int   g_cur[NNODE];
__device__ int   g_bsum[NB_SCAN];
__device__ int   g_csrc[NTOT];                        // CSR src indices
__device__ int   g_shift;                             // 1 if edge_index is int64, 0 if int32

// ---------------- small helpers -------------
__device__ __forceinline__ uint32_t smem_u32(const void* p) {
    return (uint32_t)__cvta_generic_to_shared(p);
}
__device__ __forceinline__ void cp_async16(uint32_t saddr, const void* gptr, bool pred) {
    int sz = pred ? 16 : 0;
    asm volatile("cp.async.cg.shared.global [%0], [%1], 16, %2;\n"
                 :: "r"(saddr), "l"(gptr), "r"(sz));
}
__device__ __forceinline__ void ldsm4(uint32_t& r0, uint32_t& r1, uint32_t& r2, uint32_t& r3, uint32_t a) {
    asm volatile("ldmatrix.sync.aligned.m8n8.x4.shared.b16 {%0,%1,%2,%3}, [%4];\n"
                 : "=r"(r0), "=r"(r1), "=r"(r2), "=r"(r3) : "r"(a));
}
__device__ __forceinline__ void mma_bf16(float* c, uint32_t a0, uint32_t a1, uint32_t a2, uint32_t a3,
                                         uint32_t b0, uint32_t b1) {
    asm volatile(
        "mma.sync.aligned.m16n8k16.row.col.f32.bf16.bf16.f32 "
        "{%0,%1,%2,%3},{%4,%5,%6,%7},{%8,%9},{%0,%1,%2,%3};\n"
        : "+f"(c[0]), "+f"(c[1]), "+f"(c[2]), "+f"(c[3])
        : "r"(a0), "r"(a1), "r"(a2), "r"(a3), "r"(b0), "r"(b1));
}
__device__ __forceinline__ uint16_t pack_e4m3(float lo, float hi) {
    uint16_t r;
    asm("cvt.rn.satfinite.e4m3x2.f32 %0, %1, %2;" : "=h"(r) : "f"(hi), "f"(lo));
    return r;
}
__device__ __forceinline__ float2 unpack_e4m3(uint32_t u16) {
    uint32_t h2;
    asm("cvt.rn.f16x2.e4m3x2 %0, %1;" : "=r"(h2) : "h"((uint16_t)u16));
    return __half22float2(*reinterpret_cast<__half2*>(&h2));
}

// ---------------- prep (main stream): va vectors + weight bf16 conversion ----------------
__global__ void prep_main_kernel(const float* __restrict__ W0, const float* __restrict__ a0s,
                                 const float* __restrict__ a0d,
                                 const float* __restrict__ W2, const float* __restrict__ a2s,
                                 const float* __restrict__ a2d) {
    int b = blockIdx.x, t = threadIdx.x;
    if (b == 0) {
#pragma unroll 1
        for (int v = 0; v < 16; v++) {
            int h = v & 7;
            const float* att = (v < 8) ? a0s : a0d;
            float acc = 0.f;
            for (int c = 0; c < 64; c++)
                acc = fmaf(att[h * 64 + c], W0[(size_t)(h * 64 + c) * 256 + t], acc);
            g_va0[v * 256 + t] = acc;
        }
    } else if (b == 1) {
        if (t < 64) {
#pragma unroll 1
            for (int v = 0; v < 16; v++) {
                int h = v & 7;
                const float* att = (v < 8) ? a2s : a2d;
                float acc = 0.f;
                for (int c = 0; c < 40; c++)
                    acc = fmaf(att[h * 40 + c], W2[(size_t)(h * 40 + c) * 64 + t], acc);
                g_va2[v * 64 + t] = acc;
            }
        }
    } else if (b < 514) {
        int i = (b - 2) * 256 + t;   // 512*256 = 131072
        g_w0b[i] = __float2bfloat16(W0[i]);
    } else {
        int i = (b - 514) * 256 + t; // 320*64 = 20480
        if (i < 320 * 64) g_w2b[i] = __float2bfloat16(W2[i]);
    }
}

// ---------------- prep (side stream): zero counters + dtype detect ----------------
__global__ void prep_csr_kernel(const int* __restrict__ ei) {
    int b = blockIdx.x, t = threadIdx.x;
    if (b < 196) {
        int i = b * 256 + t;
        if (i < NNODE) g_cnt[i] = 0;
    } else {
        __shared__ int s;
        if (t == 0) s = 0;
        __syncthreads();
        int v = ei[2 * t + 1];  // high words if int64 (always 0), random values if int32
        if (v != 0) atomicOr(&s, 1);
        __syncthreads();
        if (t == 0) g_shift = s ? 0 : 1;
    }
}

// ---------------- CSR build -------------
__global__ void count_kernel(const int* __restrict__ p) {
    int e = blockIdx.x * blockDim.x + threadIdx.x;
    if (e >= NTOT) return;
    int sh = g_shift;
    int dst = (e < NEDGE) ? p[(size_t)(NEDGE + e) << sh] : (e - NEDGE);
    atomicAdd(&g_cnt[dst], 1);
}
__global__ void scan1_kernel() {
    int i = blockIdx.x * 512 + threadIdx.x;
    int v = (i < NNODE) ? g_cnt[i] : 0;
    int lane = threadIdx.x & 31, w = threadIdx.x >> 5;
#pragma unroll
    for (int o = 16; o > 0; o >>= 1) v += __shfl_down_sync(0xffffffffu, v, o);
    __shared__ int ws[16];
    if (lane == 0) ws[w] = v;
    __syncthreads();
    if (w == 0) {
        int s = (lane < 16) ? ws[lane] : 0;
#pragma unroll
        for (int o = 8; o > 0; o >>= 1) s += __shfl_down_sync(0xffffffffu, s, o);
        if (lane == 0) g_bsum[blockIdx.x] = s;
    }
}
__global__ void scan2_kernel() {
    int t = threadIdx.x, lane = t & 31, w = t >> 5;
    int v = (t < NB_SCAN) ? g_bsum[t] : 0;
    int s = v;
#pragma unroll
    for (int o = 1; o < 32; o <<= 1) {
        int u = __shfl_up_sync(0xffffffffu, s, o);
        if (lane >= o) s += u;
    }
    __shared__ int wt[4];
    if (lane == 31) wt[w] = s;
    __syncthreads();
    int add = 0;
#pragma unroll
    for (int k = 0; k < 4; k++) if (k < w) add += wt[k];
    if (t < NB_SCAN) g_bsum[t] = s - v + add;
    if (t == 0) g_rs[NNODE] = wt[0] + wt[1] + wt[2] + wt[3];
}
__global__ void scan3_kernel() {
    int i = blockIdx.x * 512 + threadIdx.x;
    int t = threadIdx.x, lane = t & 31, w = t >> 5;
    int v = (i < NNODE) ? g_cnt[i] : 0;
    int s = v;
#pragma unroll
    for (int o = 1; o < 32; o <<= 1) {
        int u = __shfl_up_sync(0xffffffffu, s, o);
        if (lane >= o) s += u;
    }
    __shared__ int wt[16];
    if (lane == 31) wt[w] = s;
    __syncthreads();
    int add = g_bsum[blockIdx.x];
#pragma unroll
    for (int k = 0; k < 16; k++) if (k < w) add += wt[k];
    if (i < NNODE) {
        int e = s - v + add;
        g_rs[i] = e;
        g_cur[i] = e;
    }
}
__global__ void fill_kernel(const int* __restrict__ p) {
    int e = blockIdx.x * blockDim.x + threadIdx.x;
    if (e >= NTOT) return;
    int sh = g_shift;
    int src, dst;
    if (e < NEDGE) {
        src = p[(size_t)e << sh];
        dst = p[(size_t)(NEDGE + e) << sh];
    } else {
        src = dst = e - NEDGE;
    }
    int pos = atomicAdd(&g_cur[dst], 1);
    g_csrc[pos] = src;
}

// ---------------- node logits from x (fp32 exact) + fused x->bf16 conversion -------------
__global__ void logits0_kernel(const float* __restrict__ x) {
    __shared__ float sx[16][256];
    __shared__ float sv[16][257];
    int t = threadIdx.x;
    int nb = blockIdx.x * 16;
    for (int i = t; i < 4096; i += 256) {
        int r = i >> 8, c = i & 255;
        sv[r][c] = g_va0[i];
        int n = nb + r;
        float v = (n < NNODE) ? x[(size_t)n * 256 + c] : 0.f;
        sx[r][c] = v;
        if (n < NNODE) g_xb[(size_t)n * 256 + c] = __float2bfloat16(v);
    }
    __syncthreads();
    int ni = t >> 4, vi = t & 15;
    float acc = 0.f;
#pragma unroll 8
    for (int j = 0; j < 256; j++) acc = fmaf(sx[ni][j], sv[vi][j], acc);
    int n = nb + ni;
    if (n < NNODE) {
        if (vi < 8) g_as0[n * 8 + vi] = acc;
        else        g_ad0[n * 8 + vi - 8] = acc;
    }
}

// ---------------- bf16 tensor-core GEMM: C[M,Nc] = A[M,K] * B[Nc,K]^T ----------
template <int LAYER>
__global__ void __launch_bounds__(256, 2)
gemm_bf16_nt(int M, int Nc, int K) {
    extern __shared__ char smem[];
    const __nv_bfloat16* A  = (LAYER == 0) ? g_xb : g_hmidb;
    const __nv_bfloat16* Bw = (LAYER == 0) ? g_w0b : g_w2b;

    int tid = threadIdx.x, lane = tid & 31, w = tid >> 5;
    int bm = blockIdx.x * 128, bn = blockIdx.y * 128;
    int wm = (w & 3) * 32, wn = (w >> 2) * 64;

    float c[2][8][4];
#pragma unroll
    for (int mt = 0; mt < 2; mt++)
#pragma unroll
        for (int nt = 0; nt < 8; nt++)
#pragma unroll
            for (int j = 0; j < 4; j++) c[mt][nt][j] = 0.f;

    uint32_t sbase = smem_u32(smem);

    auto issue = [&](int s, int k0) {   // k0 in elements
#pragma unroll
        for (int i = 0; i < 4; i++) {
            int c0 = tid + i * 256;
            int row = c0 >> 3, ch = c0 & 7;
            uint32_t off = (uint32_t)(row * 128 + ch * 16) ^ (uint32_t)((row & 7) << 4);
            cp_async16(sbase + s * 16384 + off, A + (size_t)(bm + row) * K + k0 + ch * 8, bm + row < M);
            cp_async16(sbase + 32768 + s * 16384 + off, Bw + (size_t)(bn + row) * K + k0 + ch * 8, bn + row < Nc);
        }
        asm volatile("cp.async.commit_group;\n");
    };

    int a_row = (lane & 15);
    int a_cb = (lane >> 4) << 4;
    int b_row = ((lane >> 4) & 1) * 8 + (lane & 7);
    int b_cb = ((lane >> 3) & 1) << 4;

    int T = K >> 6;
    issue(0, 0);
    for (int t = 0; t < T; t++) {
        if (t + 1 < T) {
            issue((t + 1) & 1, (t + 1) << 6);
            asm volatile("cp.async.wait_group 1;\n");
        } else {
            asm volatile("cp.async.wait_group 0;\n");
        }
        __syncthreads();
        uint32_t aB = sbase + (t & 1) * 16384;
        uint32_t bB = sbase + 32768 + (t & 1) * 16384;
#pragma unroll
        for (int ks = 0; ks < 4; ks++) {
            uint32_t a[2][4], b[4][4];
#pragma unroll
            for (int mt = 0; mt < 2; mt++) {
                int row = wm + mt * 16 + a_row;
                uint32_t off = (uint32_t)(row * 128 + ks * 32 + a_cb) ^ (uint32_t)((row & 7) << 4);
                ldsm4(a[mt][0], a[mt][1], a[mt][2], a[mt][3], aB + off);
            }
#pragma unroll
            for (int pt = 0; pt < 4; pt++) {
                int row = wn + pt * 16 + b_row;
                uint32_t off = (uint32_t)(row * 128 + ks * 32 + b_cb) ^ (uint32_t)((row & 7) << 4);
                ldsm4(b[pt][0], b[pt][1], b[pt][2], b[pt][3], bB + off);
            }
#pragma unroll
            for (int mt = 0; mt < 2; mt++)
#pragma unroll
                for (int nt = 0; nt < 8; nt++) {
                    int pt = nt >> 1;
                    mma_bf16(c[mt][nt], a[mt][0], a[mt][1], a[mt][2], a[mt][3],
                             b[pt][(nt & 1) * 2], b[pt][(nt & 1) * 2 + 1]);
                }
        }
        __syncthreads();
    }
    int gr0 = bm + wm + (lane >> 2);
    int gc0 = bn + wn + (lane & 3) * 2;
#pragma unroll
    for (int mt = 0; mt < 2; mt++) {
#pragma unroll
        for (int nt = 0; nt < 8; nt++) {
            int col = gc0 + nt * 8;
            if (col < Nc) {
                int r0 = gr0 + mt * 16;
                int r1 = r0 + 8;
                if (LAYER == 0) {
                    if (r0 < M) *(uint16_t*)&g_h0f8[(size_t)r0 * Nc + col] = pack_e4m3(c[mt][nt][0], c[mt][nt][1]);
                    if (r1 < M) *(uint16_t*)&g_h0f8[(size_t)r1 * Nc + col] = pack_e4m3(c[mt][nt][2], c[mt][nt][3]);
                } else {
                    if (r0 < M) {
                        __nv_bfloat162 v = __float22bfloat162_rn(make_float2(c[mt][nt][0], c[mt][nt][1]));
                        *(__nv_bfloat162*)&g_h2b[(size_t)r0 * Nc + col] = v;
                    }
                    if (r1 < M) {
                        __nv_bfloat162 v = __float22bfloat162_rn(make_float2(c[mt][nt][2], c[mt][nt][3]));
                        *(__nv_bfloat162*)&g_h2b[(size_t)r1 * Nc + col] = v;
                    }
                }
            }
        }
    }
}

// ---------------- layer0 pull: one node/warp, 4x unroll, fused logits2 ----------------
__global__ void __launch_bounds__(256) pull0_kernel(const float* __restrict__ b0) {
    __shared__ float sva[16 * 64];
    __shared__ float sb0[64];
    int t = threadIdx.x, lane = t & 31;
    for (int i = t; i < 1024; i += 256) sva[i] = g_va2[i];
    if (t < 64) sb0[t] = b0[t];
    __syncthreads();
    int gw = (blockIdx.x * blockDim.x + t) >> 5;
    if (gw >= NNODE) return;
    int head = lane >> 2, colg = lane & 3;

    float sd = g_ad0[gw * 8 + head];
    int beg = g_rs[gw], end = g_rs[gw + 1];
    float acc[16];
#pragma unroll
    for (int j = 0; j < 16; j++) acc[j] = 0.f;
    float wsum = 0.f;

    int i = beg;
    for (; i + 4 <= end; i += 4) {
        int s0 = g_csrc[i], s1 = g_csrc[i + 1], s2 = g_csrc[i + 2], s3 = g_csrc[i + 3];
        float l0 = g_as0[s0 * 8 + head], l1 = g_as0[s1 * 8 + head];
        float l2 = g_as0[s2 * 8 + head], l3 = g_as0[s3 * 8 + head];
        uint4 u0 = *(const uint4*)(g_h0f8 + (size_t)s0 * 512 + lane * 16);
        uint4 u1 = *(const uint4*)(g_h0f8 + (size_t)s1 * 512 + lane * 16);
        uint4 u2 = *(const uint4*)(g_h0f8 + (size_t)s2 * 512 + lane * 16);
        uint4 u3 = *(const uint4*)(g_h0f8 + (size_t)s3 * 512 + lane * 16);
        float e0 = l0 + sd; e0 = e0 > 0.f ? e0 : 0.2f * e0;
        float e1 = l1 + sd; e1 = e1 > 0.f ? e1 : 0.2f * e1;
        float e2 = l2 + sd; e2 = e2 > 0.f ? e2 : 0.2f * e2;
        float e3 = l3 + sd; e3 = e3 > 0.f ? e3 : 0.2f * e3;
        float w0 = __expf(e0), w1 = __expf(e1), w2 = __expf(e2), w3 = __expf(e3);
        wsum += (w0 + w1) + (w2 + w3);
        const uint32_t* p0 = &u0.x;
        const uint32_t* p1 = &u1.x;
        const uint32_t* p2 = &u2.x;
        const uint32_t* p3 = &u3.x;
#pragma unroll
        for (int q = 0; q < 4; q++) {
            float2 a0 = unpack_e4m3(p0[q] & 0xffffu), a1 = unpack_e4m3(p0[q] >> 16);
            float2 c0 = unpack_e4m3(p1[q] & 0xffffu), c1 = unpack_e4m3(p1[q] >> 16);
            float2 d0 = unpack_e4m3(p2[q] & 0xffffu), d1 = unpack_e4m3(p2[q] >> 16);
            float2 f0 = unpack_e4m3(p3[q] & 0xffffu), f1 = unpack_e4m3(p3[q] >> 16);
            acc[q * 4 + 0] = fmaf(w3, f0.x, fmaf(w2, d0.x, fmaf(w1, c0.x, fmaf(w0, a0.x, acc[q * 4 + 0]))));
            acc[q * 4 + 1] = fmaf(w3, f0.y, fmaf(w2, d0.y, fmaf(w1, c0.y, fmaf(w0, a0.y, acc[q * 4 + 1]))));
            acc[q * 4 + 2] = fmaf(w3, f1.x, fmaf(w2, d1.x, fmaf(w1, c1.x, fmaf(w0, a1.x, acc[q * 4 + 2]))));
            acc[q * 4 + 3] = fmaf(w3, f1.y, fmaf(w2, d1.y, fmaf(w1, c1.y, fmaf(w0, a1.y, acc[q * 4 + 3]))));
        }
    }
    for (; i < end; i++) {
        int s0 = g_csrc[i];
        float el = g_as0[s0 * 8 + head] + sd;
        el = el > 0.f ? el : 0.2f * el;
        float w0 = __expf(el);
        wsum += w0;
        uint4 ua = *(const uint4*)(g_h0f8 + (size_t)s0 * 512 + lane * 16);
        const uint32_t va[4] = {ua.x, ua.y, ua.z, ua.w};
#pragma unroll
        for (int q = 0; q < 4; q++) {
            float2 a0 = unpack_e4m3(va[q] & 0xffffu);
            float2 a1 = unpack_e4m3(va[q] >> 16);
            acc[q * 4 + 0] = fmaf(w0, a0.x, acc[q * 4 + 0]);
            acc[q * 4 + 1] = fmaf(w0, a0.y, acc[q * 4 + 1]);
            acc[q * 4 + 2] = fmaf(w0, a1.x, acc[q * 4 + 2]);
            acc[q * 4 + 3] = fmaf(w0, a1.y, acc[q * 4 + 3]);
        }
    }

    float inv = 1.f / (wsum + 1e-16f);
#pragma unroll
    for (int j = 0; j < 16; j++) acc[j] *= inv;
#pragma unroll
    for (int j = 0; j < 16; j++) {
        acc[j] += __shfl_xor_sync(0xffffffffu, acc[j], 4);
        acc[j] += __shfl_xor_sync(0xffffffffu, acc[j], 8);
        acc[j] += __shfl_xor_sync(0xffffffffu, acc[j], 16);
    }
    // every lane now holds mean-head values for cols colg*16 .. colg*16+15
    float o[16];
#pragma unroll
    for (int j = 0; j < 16; j++) {
        float r = acc[j] * 0.125f + sb0[colg * 16 + j];
        o[j] = r > 0.f ? r : 0.f;
    }
    if (lane < 4) {
        __nv_bfloat162* op = (__nv_bfloat162*)(g_hmidb + (size_t)gw * 64 + lane * 16);
#pragma unroll
        for (int q = 0; q < 8; q++)
            op[q] = __float22bfloat162_rn(make_float2(o[q * 2], o[q * 2 + 1]));
    }
    // fused layer-2 logits: d_v = hmid . va2[v]  (fp32, pre-rounding)
#pragma unroll 1
    for (int v = 0; v < 16; v++) {
        float d = 0.f;
        const float* vp = &sva[v * 64 + colg * 16];
#pragma unroll
        for (int j = 0; j < 16; j++) d = fmaf(o[j], vp[j], d);
        d += __shfl_xor_sync(0xffffffffu, d, 1);
        d += __shfl_xor_sync(0xffffffffu, d, 2);
        if (lane == v) {
            if (v < 8) g_as2[gw * 8 + v] = d;
            else       g_ad2[gw * 8 + v - 8] = d;
        }
    }
}

// ---------------- layer2 pull: one node/warp, 4x unroll, fused log_softmax ----------
__global__ void __launch_bounds__(256) pull2_kernel(const float* __restrict__ b2, float* __restrict__ out) {
    int t = threadIdx.x, lane = t & 31;
    int gw = (blockIdx.x * blockDim.x + t) >> 5;
    if (gw >= NNODE) return;
    int head = lane >> 2;

    float sd = g_ad2[gw * 8 + head];
    int beg = g_rs[gw], end = g_rs[gw + 1];
    float acc[10];
#pragma unroll
    for (int j = 0; j < 10; j++) acc[j] = 0.f;
    float wsum = 0.f;

    int i = beg;
    for (; i + 4 <= end; i += 4) {
        int s0 = g_csrc[i], s1 = g_csrc[i + 1], s2 = g_csrc[i + 2], s3 = g_csrc[i + 3];
        float l0 = g_as2[s0 * 8 + head], l1 = g_as2[s1 * 8 + head];
        float l2 = g_as2[s2 * 8 + head], l3 = g_as2[s3 * 8 + head];
        const uint32_t* p0 = (const uint32_t*)(g_h2b + (size_t)s0 * 320 + lane * 10);
        const uint32_t* p1 = (const uint32_t*)(g_h2b + (size_t)s1 * 320 + lane * 10);
        const uint32_t* p2 = (const uint32_t*)(g_h2b + (size_t)s2 * 320 + lane * 10);
        const uint32_t* p3 = (const uint32_t*)(g_h2b + (size_t)s3 * 320 + lane * 10);
        uint32_t ua[5], ub[5], uc[5], ud[5];
#pragma unroll
        for (int q = 0; q < 5; q++) { ua[q] = p0[q]; ub[q] = p1[q]; uc[q] = p2[q]; ud[q] = p3[q]; }
        float e0 = l0 + sd; e0 = e0 > 0.f ? e0 : 0.2f * e0;
        float e1 = l1 + sd; e1 = e1 > 0.f ? e1 : 0.2f * e1;
        float e2 = l2 + sd; e2 = e2 > 0.f ? e2 : 0.2f * e2;
        float e3 = l3 + sd; e3 = e3 > 0.f ? e3 : 0.2f * e3;
        float w0 = __expf(e0), w1 = __expf(e1), w2 = __expf(e2), w3 = __expf(e3);
        wsum += (w0 + w1) + (w2 + w3);
#pragma unroll
        for (int q = 0; q < 5; q++) {
            float2 f0 = __bfloat1622float2(*(const __nv_bfloat162*)&ua[q]);
            float2 f1 = __bfloat1622float2(*(const __nv_bfloat162*)&ub[q]);
            float2 f2 = __bfloat1622float2(*(const __nv_bfloat162*)&uc[q]);
            float2 f3 = __bfloat1622float2(*(const __nv_bfloat162*)&ud[q]);
            acc[q * 2 + 0] = fmaf(w3, f3.x, fmaf(w2, f2.x, fmaf(w1, f1.x, fmaf(w0, f0.x, acc[q * 2 + 0]))));
            acc[q * 2 + 1] = fmaf(w3, f3.y, fmaf(w2, f2.y, fmaf(w1, f1.y, fmaf(w0, f0.y, acc[q * 2 + 1]))));
        }
    }
    for (; i < end; i++) {
        int s0 = g_csrc[i];
        float el = g_as2[s0 * 8 + head] + sd;
        el = el > 0.f ? el : 0.2f * el;
        float w0 = __expf(el);
        wsum += w0;
        const uint32_t* p0 = (const uint32_t*)(g_h2b + (size_t)s0 * 320 + lane * 10);
        uint32_t uu[5];
#pragma unroll
        for (int q = 0; q < 5; q++) uu[q] = p0[q];
#pragma unroll
        for (int q = 0; q < 5; q++) {
            float2 f = __bfloat1622float2(*(const __nv_bfloat162*)&uu[q]);
            acc[q * 2 + 0] = fmaf(w0, f.x, acc[q * 2 + 0]);
            acc[q * 2 + 1] = fmaf(w0, f.y, acc[q * 2 + 1]);
        }
    }

    float inv = 1.f / (wsum + 1e-16f);
#pragma unroll
    for (int j = 0; j < 10; j++) acc[j] *= inv;
#pragma unroll
    for (int j = 0; j < 10; j++) {
        acc[j] += __shfl_xor_sync(0xffffffffu, acc[j], 4);
        acc[j] += __shfl_xor_sync(0xffffffffu, acc[j], 8);
        acc[j] += __shfl_xor_sync(0xffffffffu, acc[j], 16);
    }
    int co = (lane & 3) * 10;
    float val[10];
    float vmax = -1e30f;
#pragma unroll
    for (int j = 0; j < 10; j++) {
        val[j] = acc[j] * 0.125f + b2[co + j];
        vmax = fmaxf(vmax, val[j]);
    }
    vmax = fmaxf(vmax, __shfl_xor_sync(0xffffffffu, vmax, 1));
    vmax = fmaxf(vmax, __shfl_xor_sync(0xffffffffu, vmax, 2));
    float se = 0.f;
#pragma unroll
    for (int j = 0; j < 10; j++) se += __expf(val[j] - vmax);
    se += __shfl_xor_sync(0xffffffffu, se, 1);
    se += __shfl_xor_sync(0xffffffffu, se, 2);
    float lse = vmax + logf(se);
    if (lane < 4) {
        float* op = out + (size_t)gw * 40 + co;
#pragma unroll
        for (int q = 0; q < 5; q++)
            *(float2*)&op[q * 2] = make_float2(val[q * 2] - lse, val[q * 2 + 1] - lse);
    }
}

// ---------------- launcher (forked-stream graph: CSR build || GEMM path) -----------------
extern "C" void kernel_launch(void* const* d_in, const int* in_sizes, int n_in,
                              void* d_out, int out_size) {
    const float* x   = (const float*)d_in[0];
    const int*   ei  = (const int*)d_in[1];
    // d_in[2] = edge_attr (unused by GATConv)
    const float* W0  = (const float*)d_in[3];
    const float* a0s = (const float*)d_in[4];
    const float* a0d = (const float*)d_in[5];
    const float* b0  = (const float*)d_in[6];
    const float* W2  = (const float*)d_in[7];
    const float* a2s = (const float*)d_in[8];
    const float* a2d = (const float*)d_in[9];
    const float* b2  = (const float*)d_in[10];
    float* out = (float*)d_out;

    static cudaStream_t s2 = nullptr;
    static cudaEvent_t evA = nullptr, evB = nullptr;
    if (!s2) {
        cudaStreamCreateWithFlags(&s2, cudaStreamNonBlocking);
        cudaEventCreateWithFlags(&evA, cudaEventDisableTiming);
        cudaEventCreateWithFlags(&evB, cudaEventDisableTiming);
        cudaFuncSetAttribute(gemm_bf16_nt<0>, cudaFuncAttributeMaxDynamicSharedMemorySize, 65536);
        cudaFuncSetAttribute(gemm_bf16_nt<1>, cudaFuncAttributeMaxDynamicSharedMemorySize, 65536);
    }

    // fork: CSR build chain on s2, compute chain on main stream
    cudaEventRecord(evA, 0);
    cudaStreamWaitEvent(s2, evA, 0);

    prep_csr_kernel<<<197, 256, 0, s2>>>(ei);
    count_kernel<<<(NTOT + 255) / 256, 256, 0, s2>>>(ei);
    scan1_kernel<<<NB_SCAN, 512, 0, s2>>>();
    scan2_kernel<<<1, 128, 0, s2>>>();
    scan3_kernel<<<NB_SCAN, 512, 0, s2>>>();
    fill_kernel<<<(NTOT + 255) / 256, 256, 0, s2>>>(ei);
    cudaEventRecord(evB, s2);

    prep_main_kernel<<<594, 256>>>(W0, a0s, a0d, W2, a2s, a2d);
    logits0_kernel<<<3125, 256>>>(x);
    gemm_bf16_nt<0><<<dim3(391, 4), 256, 65536>>>(NNODE, 512, 256);

    cudaStreamWaitEvent(0, evB, 0);
    pull0_kernel<<<6250, 256>>>(b0);

    gemm_bf16_nt<1><<<dim3(391, 3), 256, 65536>>>(NNODE, 320, 64);
    pull2_kernel<<<6250, 256>>>(b2, out);
}

// round 11
// speedup vs baseline: 1.2659x; 1.2147x over previous
#include <cuda_runtime.h>
#include <cuda_bf16.h>
#include <cuda_fp16.h>
#include <cstdint>
#include <cstddef>

#define NNODE 50000
#define NEDGE 800000
#define NTOT  850000   // edges + self loops
#define HEADS 8
#define NB_SCAN 98     // ceil(NNODE/512)

// ---------------- scratch (device globals; no allocations allowed) -------------
__device__ uint8_t g_h0f8[(size_t)NNODE * 512];       // layer0 features e4m3 [N][8][64]
__device__ __nv_bfloat16 g_h2b[(size_t)NNODE * 320];  // layer2 features bf16 [N][8][40]
__device__ __nv_bfloat16 g_xb[(size_t)NNODE * 256];   // input x in bf16
__device__ __nv_bfloat16 g_hmidb[(size_t)NNODE * 64]; // relu(mean-head layer0) bf16
__device__ __nv_bfloat16 g_w0b[512 * 256];            // W0 bf16
__device__ __nv_bfloat16 g_w2b[320 * 64];             // W2 bf16
__device__ float g_as0[NNODE * 8], g_ad0[NNODE * 8];
__device__ float g_as2[NNODE * 8], g_ad2[NNODE * 8];
__device__ float g_va0[16 * 256];                     // folded attention vecs (fp32 exact)
__device__ float g_va2[16 * 64];
__device__ int   g_cnt[NNODE];
__device__ int   g_rs[NNODE + 1];                     // CSR row_start by dst
__device__ int   g_cur[NNODE];
__device__ int   g_bsum[NB_SCAN];
__device__ int   g_csrc[NTOT];                        // CSR src indices
__device__ int   g_shift;                             // 1 if edge_index is int64, 0 if int32

// ---------------- small helpers -------------
__device__ __forceinline__ uint32_t smem_u32(const void* p) {
    return (uint32_t)__cvta_generic_to_shared(p);
}
__device__ __forceinline__ void cp_async16(uint32_t saddr, const void* gptr, bool pred) {
    int sz = pred ? 16 : 0;
    asm volatile("cp.async.cg.shared.global [%0], [%1], 16, %2;\n"
                 :: "r"(saddr), "l"(gptr), "r"(sz));
}
__device__ __forceinline__ void ldsm4(uint32_t& r0, uint32_t& r1, uint32_t& r2, uint32_t& r3, uint32_t a) {
    asm volatile("ldmatrix.sync.aligned.m8n8.x4.shared.b16 {%0,%1,%2,%3}, [%4];\n"
                 : "=r"(r0), "=r"(r1), "=r"(r2), "=r"(r3) : "r"(a));
}
__device__ __forceinline__ void mma_bf16(float* c, uint32_t a0, uint32_t a1, uint32_t a2, uint32_t a3,
                                         uint32_t b0, uint32_t b1) {
    asm volatile(
        "mma.sync.aligned.m16n8k16.row.col.f32.bf16.bf16.f32 "
        "{%0,%1,%2,%3},{%4,%5,%6,%7},{%8,%9},{%0,%1,%2,%3};\n"
        : "+f"(c[0]), "+f"(c[1]), "+f"(c[2]), "+f"(c[3])
        : "r"(a0), "r"(a1), "r"(a2), "r"(a3), "r"(b0), "r"(b1));
}
__device__ __forceinline__ uint16_t pack_e4m3(float lo, float hi) {
    uint16_t r;
    asm("cvt.rn.satfinite.e4m3x2.f32 %0, %1, %2;" : "=h"(r) : "f"(hi), "f"(lo));
    return r;
}
__device__ __forceinline__ float2 unpack_e4m3(uint32_t u16) {
    uint32_t h2;
    asm("cvt.rn.f16x2.e4m3x2 %0, %1;" : "=r"(h2) : "h"((uint16_t)u16));
    return __half22float2(*reinterpret_cast<__half2*>(&h2));
}

// ---------------- prep (main stream): va vectors + weight bf16 conversion ----------------
__global__ void prep_main_kernel(const float* __restrict__ W0, const float* __restrict__ a0s,
                                 const float* __restrict__ a0d,
                                 const float* __restrict__ W2, const float* __restrict__ a2s,
                                 const float* __restrict__ a2d) {
    int b = blockIdx.x, t = threadIdx.x;
    if (b == 0) {
#pragma unroll 1
        for (int v = 0; v < 16; v++) {
            int h = v & 7;
            const float* att = (v < 8) ? a0s : a0d;
            float acc = 0.f;
            for (int c = 0; c < 64; c++)
                acc = fmaf(att[h * 64 + c], W0[(size_t)(h * 64 + c) * 256 + t], acc);
            g_va0[v * 256 + t] = acc;
        }
    } else if (b == 1) {
        if (t < 64) {
#pragma unroll 1
            for (int v = 0; v < 16; v++) {
                int h = v & 7;
                const float* att = (v < 8) ? a2s : a2d;
                float acc = 0.f;
                for (int c = 0; c < 40; c++)
                    acc = fmaf(att[h * 40 + c], W2[(size_t)(h * 40 + c) * 64 + t], acc);
                g_va2[v * 64 + t] = acc;
            }
        }
    } else if (b < 514) {
        int i = (b - 2) * 256 + t;   // 512*256 = 131072
        g_w0b[i] = __float2bfloat16(W0[i]);
    } else {
        int i = (b - 514) * 256 + t; // 320*64 = 20480
        if (i < 320 * 64) g_w2b[i] = __float2bfloat16(W2[i]);
    }
}

// ---------------- x -> bf16 conversion (main stream, feeds gemm0) ----------------
__global__ void xconv_kernel(const float* __restrict__ x) {
    int i = blockIdx.x * 256 + threadIdx.x;   // float4 index; 12.8M/4 = 3.2M
    float4 v = ((const float4*)x)[i];
    uint2* op = (uint2*)(g_xb + (size_t)i * 4);
    __nv_bfloat162 lo = __float22bfloat162_rn(make_float2(v.x, v.y));
    __nv_bfloat162 hi = __float22bfloat162_rn(make_float2(v.z, v.w));
    uint2 o;
    o.x = *(uint32_t*)&lo;
    o.y = *(uint32_t*)&hi;
    *op = o;
}

// ---------------- prep (side stream): zero counters + dtype detect ----------------
__global__ void prep_csr_kernel(const int* __restrict__ ei) {
    int b = blockIdx.x, t = threadIdx.x;
    if (b < 196) {
        int i = b * 256 + t;
        if (i < NNODE) g_cnt[i] = 0;
    } else {
        __shared__ int s;
        if (t == 0) s = 0;
        __syncthreads();
        int v = ei[2 * t + 1];  // high words if int64 (always 0), random values if int32
        if (v != 0) atomicOr(&s, 1);
        __syncthreads();
        if (t == 0) g_shift = s ? 0 : 1;
    }
}

// ---------------- CSR build -------------
__global__ void count_kernel(const int* __restrict__ p) {
    int e = blockIdx.x * blockDim.x + threadIdx.x;
    if (e >= NTOT) return;
    int sh = g_shift;
    int dst = (e < NEDGE) ? p[(size_t)(NEDGE + e) << sh] : (e - NEDGE);
    atomicAdd(&g_cnt[dst], 1);
}
__global__ void scan1_kernel() {
    int i = blockIdx.x * 512 + threadIdx.x;
    int v = (i < NNODE) ? g_cnt[i] : 0;
    int lane = threadIdx.x & 31, w = threadIdx.x >> 5;
#pragma unroll
    for (int o = 16; o > 0; o >>= 1) v += __shfl_down_sync(0xffffffffu, v, o);
    __shared__ int ws[16];
    if (lane == 0) ws[w] = v;
    __syncthreads();
    if (w == 0) {
        int s = (lane < 16) ? ws[lane] : 0;
#pragma unroll
        for (int o = 8; o > 0; o >>= 1) s += __shfl_down_sync(0xffffffffu, s, o);
        if (lane == 0) g_bsum[blockIdx.x] = s;
    }
}
__global__ void scan2_kernel() {
    int t = threadIdx.x, lane = t & 31, w = t >> 5;
    int v = (t < NB_SCAN) ? g_bsum[t] : 0;
    int s = v;
#pragma unroll
    for (int o = 1; o < 32; o <<= 1) {
        int u = __shfl_up_sync(0xffffffffu, s, o);
        if (lane >= o) s += u;
    }
    __shared__ int wt[4];
    if (lane == 31) wt[w] = s;
    __syncthreads();
    int add = 0;
#pragma unroll
    for (int k = 0; k < 4; k++) if (k < w) add += wt[k];
    if (t < NB_SCAN) g_bsum[t] = s - v + add;
    if (t == 0) g_rs[NNODE] = wt[0] + wt[1] + wt[2] + wt[3];
}
__global__ void scan3_kernel() {
    int i = blockIdx.x * 512 + threadIdx.x;
    int t = threadIdx.x, lane = t & 31, w = t >> 5;
    int v = (i < NNODE) ? g_cnt[i] : 0;
    int s = v;
#pragma unroll
    for (int o = 1; o < 32; o <<= 1) {
        int u = __shfl_up_sync(0xffffffffu, s, o);
        if (lane >= o) s += u;
    }
    __shared__ int wt[16];
    if (lane == 31) wt[w] = s;
    __syncthreads();
    int add = g_bsum[blockIdx.x];
#pragma unroll
    for (int k = 0; k < 16; k++) if (k < w) add += wt[k];
    if (i < NNODE) {
        int e = s - v + add;
        g_rs[i] = e;
        g_cur[i] = e;
    }
}
__global__ void fill_kernel(const int* __restrict__ p) {
    int e = blockIdx.x * blockDim.x + threadIdx.x;
    if (e >= NTOT) return;
    int sh = g_shift;
    int src, dst;
    if (e < NEDGE) {
        src = p[(size_t)e << sh];
        dst = p[(size_t)(NEDGE + e) << sh];
    } else {
        src = dst = e - NEDGE;
    }
    int pos = atomicAdd(&g_cur[dst], 1);
    g_csrc[pos] = src;
}

// ---------------- node logits from x (fp32 exact, runs on side stream) -------------
__global__ void logits0_kernel(const float* __restrict__ x) {
    __shared__ float sx[16][256];
    __shared__ float sv[16][257];
    int t = threadIdx.x;
    int nb = blockIdx.x * 16;
    for (int i = t; i < 4096; i += 256) {
        int r = i >> 8, c = i & 255;
        sv[r][c] = g_va0[i];
        int n = nb + r;
        sx[r][c] = (n < NNODE) ? x[(size_t)n * 256 + c] : 0.f;
    }
    __syncthreads();
    int ni = t >> 4, vi = t & 15;
    float acc = 0.f;
#pragma unroll 8
    for (int j = 0; j < 256; j++) acc = fmaf(sx[ni][j], sv[vi][j], acc);
    int n = nb + ni;
    if (n < NNODE) {
        if (vi < 8) g_as0[n * 8 + vi] = acc;
        else        g_ad0[n * 8 + vi - 8] = acc;
    }
}
__global__ void logits2_kernel() {
    __shared__ float sx[16][64];
    __shared__ float sv[16][65];
    int t = threadIdx.x;
    int nb = blockIdx.x * 16;
    for (int i = t; i < 1024; i += 256) {
        int r = i >> 6, c = i & 63;
        sv[r][c] = g_va2[i];
        int n = nb + r;
        sx[r][c] = (n < NNODE) ? __bfloat162float(g_hmidb[(size_t)n * 64 + c]) : 0.f;
    }
    __syncthreads();
    int ni = t >> 4, vi = t & 15;
    float acc = 0.f;
#pragma unroll
    for (int j = 0; j < 64; j++) acc = fmaf(sx[ni][j], sv[vi][j], acc);
    int n = nb + ni;
    if (n < NNODE) {
        if (vi < 8) g_as2[n * 8 + vi] = acc;
        else        g_ad2[n * 8 + vi - 8] = acc;
    }
}

// ---------------- bf16 tensor-core GEMM: C[M,Nc] = A[M,K] * B[Nc,K]^T ----------
template <int LAYER>
__global__ void __launch_bounds__(256, 2)
gemm_bf16_nt(int M, int Nc, int K) {
    extern __shared__ char smem[];
    const __nv_bfloat16* A  = (LAYER == 0) ? g_xb : g_hmidb;
    const __nv_bfloat16* Bw = (LAYER == 0) ? g_w0b : g_w2b;

    int tid = threadIdx.x, lane = tid & 31, w = tid >> 5;
    int bm = blockIdx.x * 128, bn = blockIdx.y * 128;
    int wm = (w & 3) * 32, wn = (w >> 2) * 64;

    float c[2][8][4];
#pragma unroll
    for (int mt = 0; mt < 2; mt++)
#pragma unroll
        for (int nt = 0; nt < 8; nt++)
#pragma unroll
            for (int j = 0; j < 4; j++) c[mt][nt][j] = 0.f;

    uint32_t sbase = smem_u32(smem);

    auto issue = [&](int s, int k0) {   // k0 in elements
#pragma unroll
        for (int i = 0; i < 4; i++) {
            int c0 = tid + i * 256;
            int row = c0 >> 3, ch = c0 & 7;
            uint32_t off = (uint32_t)(row * 128 + ch * 16) ^ (uint32_t)((row & 7) << 4);
            cp_async16(sbase + s * 16384 + off, A + (size_t)(bm + row) * K + k0 + ch * 8, bm + row < M);
            cp_async16(sbase + 32768 + s * 16384 + off, Bw + (size_t)(bn + row) * K + k0 + ch * 8, bn + row < Nc);
        }
        asm volatile("cp.async.commit_group;\n");
    };

    int a_row = (lane & 15);
    int a_cb = (lane >> 4) << 4;
    int b_row = ((lane >> 4) & 1) * 8 + (lane & 7);
    int b_cb = ((lane >> 3) & 1) << 4;

    int T = K >> 6;
    issue(0, 0);
    for (int t = 0; t < T; t++) {
        if (t + 1 < T) {
            issue((t + 1) & 1, (t + 1) << 6);
            asm volatile("cp.async.wait_group 1;\n");
        } else {
            asm volatile("cp.async.wait_group 0;\n");
        }
        __syncthreads();
        uint32_t aB = sbase + (t & 1) * 16384;
        uint32_t bB = sbase + 32768 + (t & 1) * 16384;
#pragma unroll
        for (int ks = 0; ks < 4; ks++) {
            uint32_t a[2][4], b[4][4];
#pragma unroll
            for (int mt = 0; mt < 2; mt++) {
                int row = wm + mt * 16 + a_row;
                uint32_t off = (uint32_t)(row * 128 + ks * 32 + a_cb) ^ (uint32_t)((row & 7) << 4);
                ldsm4(a[mt][0], a[mt][1], a[mt][2], a[mt][3], aB + off);
            }
#pragma unroll
            for (int pt = 0; pt < 4; pt++) {
                int row = wn + pt * 16 + b_row;
                uint32_t off = (uint32_t)(row * 128 + ks * 32 + b_cb) ^ (uint32_t)((row & 7) << 4);
                ldsm4(b[pt][0], b[pt][1], b[pt][2], b[pt][3], bB + off);
            }
#pragma unroll
            for (int mt = 0; mt < 2; mt++)
#pragma unroll
                for (int nt = 0; nt < 8; nt++) {
                    int pt = nt >> 1;
                    mma_bf16(c[mt][nt], a[mt][0], a[mt][1], a[mt][2], a[mt][3],
                             b[pt][(nt & 1) * 2], b[pt][(nt & 1) * 2 + 1]);
                }
        }
        __syncthreads();
    }
    int gr0 = bm + wm + (lane >> 2);
    int gc0 = bn + wn + (lane & 3) * 2;
#pragma unroll
    for (int mt = 0; mt < 2; mt++) {
#pragma unroll
        for (int nt = 0; nt < 8; nt++) {
            int col = gc0 + nt * 8;
            if (col < Nc) {
                int r0 = gr0 + mt * 16;
                int r1 = r0 + 8;
                if (LAYER == 0) {
                    if (r0 < M) *(uint16_t*)&g_h0f8[(size_t)r0 * Nc + col] = pack_e4m3(c[mt][nt][0], c[mt][nt][1]);
                    if (r1 < M) *(uint16_t*)&g_h0f8[(size_t)r1 * Nc + col] = pack_e4m3(c[mt][nt][2], c[mt][nt][3]);
                } else {
                    if (r0 < M) {
                        __nv_bfloat162 v = __float22bfloat162_rn(make_float2(c[mt][nt][0], c[mt][nt][1]));
                        *(__nv_bfloat162*)&g_h2b[(size_t)r0 * Nc + col] = v;
                    }
                    if (r1 < M) {
                        __nv_bfloat162 v = __float22bfloat162_rn(make_float2(c[mt][nt][2], c[mt][nt][3]));
                        *(__nv_bfloat162*)&g_h2b[(size_t)r1 * Nc + col] = v;
                    }
                }
            }
        }
    }
}

// ---------------- layer0 pull aggregation (fp8 gather, 2x unroll) ----
__global__ void pull0_kernel(const float* __restrict__ b0) {
    int gw = (blockIdx.x * blockDim.x + threadIdx.x) >> 5;
    int lane = threadIdx.x & 31;
    if (gw >= NNODE) return;
    int head = lane >> 2;
    float sd = g_ad0[gw * 8 + head];
    int beg = g_rs[gw], end = g_rs[gw + 1];
    float acc[16];
#pragma unroll
    for (int j = 0; j < 16; j++) acc[j] = 0.f;
    float wsum = 0.f;
    int i = beg;
    for (; i + 2 <= end; i += 2) {
        int s0 = g_csrc[i], s1 = g_csrc[i + 1];
        float l0 = g_as0[s0 * 8 + head], l1 = g_as0[s1 * 8 + head];
        uint4 ua = *(const uint4*)(g_h0f8 + (size_t)s0 * 512 + lane * 16);
        uint4 ub = *(const uint4*)(g_h0f8 + (size_t)s1 * 512 + lane * 16);
        float e0 = l0 + sd; e0 = e0 > 0.f ? e0 : 0.2f * e0;
        float e1 = l1 + sd; e1 = e1 > 0.f ? e1 : 0.2f * e1;
        float w0 = __expf(e0), w1 = __expf(e1);
        wsum += w0 + w1;
        const uint32_t va[4] = {ua.x, ua.y, ua.z, ua.w};
        const uint32_t vb[4] = {ub.x, ub.y, ub.z, ub.w};
#pragma unroll
        for (int q = 0; q < 4; q++) {
            float2 a0 = unpack_e4m3(va[q] & 0xffffu);
            float2 a1 = unpack_e4m3(va[q] >> 16);
            float2 c0 = unpack_e4m3(vb[q] & 0xffffu);
            float2 c1 = unpack_e4m3(vb[q] >> 16);
            acc[q * 4 + 0] = fmaf(w1, c0.x, fmaf(w0, a0.x, acc[q * 4 + 0]));
            acc[q * 4 + 1] = fmaf(w1, c0.y, fmaf(w0, a0.y, acc[q * 4 + 1]));
            acc[q * 4 + 2] = fmaf(w1, c1.x, fmaf(w0, a1.x, acc[q * 4 + 2]));
            acc[q * 4 + 3] = fmaf(w1, c1.y, fmaf(w0, a1.y, acc[q * 4 + 3]));
        }
    }
    if (i < end) {
        int s0 = g_csrc[i];
        float el = g_as0[s0 * 8 + head] + sd;
        el = el > 0.f ? el : 0.2f * el;
        float w0 = __expf(el);
        wsum += w0;
        uint4 ua = *(const uint4*)(g_h0f8 + (size_t)s0 * 512 + lane * 16);
        const uint32_t va[4] = {ua.x, ua.y, ua.z, ua.w};
#pragma unroll
        for (int q = 0; q < 4; q++) {
            float2 a0 = unpack_e4m3(va[q] & 0xffffu);
            float2 a1 = unpack_e4m3(va[q] >> 16);
            acc[q * 4 + 0] = fmaf(w0, a0.x, acc[q * 4 + 0]);
            acc[q * 4 + 1] = fmaf(w0, a0.y, acc[q * 4 + 1]);
            acc[q * 4 + 2] = fmaf(w0, a1.x, acc[q * 4 + 2]);
            acc[q * 4 + 3] = fmaf(w0, a1.y, acc[q * 4 + 3]);
        }
    }
    float inv = 1.f / (wsum + 1e-16f);
#pragma unroll
    for (int j = 0; j < 16; j++) acc[j] *= inv;
#pragma unroll
    for (int j = 0; j < 16; j++) {
        acc[j] += __shfl_xor_sync(0xffffffffu, acc[j], 4);
        acc[j] += __shfl_xor_sync(0xffffffffu, acc[j], 8);
        acc[j] += __shfl_xor_sync(0xffffffffu, acc[j], 16);
    }
    if (lane < 4) {
        __nv_bfloat162* op = (__nv_bfloat162*)(g_hmidb + (size_t)gw * 64 + lane * 16);
#pragma unroll
        for (int q = 0; q < 8; q++) {
            float r0 = acc[q * 2 + 0] * 0.125f + b0[lane * 16 + q * 2 + 0];
            float r1 = acc[q * 2 + 1] * 0.125f + b0[lane * 16 + q * 2 + 1];
            r0 = r0 > 0.f ? r0 : 0.f;
            r1 = r1 > 0.f ? r1 : 0.f;
            op[q] = __float22bfloat162_rn(make_float2(r0, r1));
        }
    }
}

// ---------------- layer2 pull aggregation (bf16 gather, 2x unroll, fused log_softmax) ----
__global__ void pull2_kernel(const float* __restrict__ b2, float* __restrict__ out) {
    __shared__ float sb2[40];
    int t = threadIdx.x, lane = t & 31;
    if (t < 40) sb2[t] = b2[t];
    __syncthreads();
    int gw = (blockIdx.x * blockDim.x + t) >> 5;
    if (gw >= NNODE) return;
    int head = lane >> 2;
    float sd = g_ad2[gw * 8 + head];
    int beg = g_rs[gw], end = g_rs[gw + 1];
    float acc[10];
#pragma unroll
    for (int j = 0; j < 10; j++) acc[j] = 0.f;
    float wsum = 0.f;
    int i = beg;
    for (; i + 2 <= end; i += 2) {
        int s0 = g_csrc[i], s1 = g_csrc[i + 1];
        float l0 = g_as2[s0 * 8 + head], l1 = g_as2[s1 * 8 + head];
        const uint32_t* p0 = (const uint32_t*)(g_h2b + (size_t)s0 * 320 + lane * 10);
        const uint32_t* p1 = (const uint32_t*)(g_h2b + (size_t)s1 * 320 + lane * 10);
        uint32_t ua[5], ub[5];
#pragma unroll
        for (int q = 0; q < 5; q++) { ua[q] = p0[q]; ub[q] = p1[q]; }
        float e0 = l0 + sd; e0 = e0 > 0.f ? e0 : 0.2f * e0;
        float e1 = l1 + sd; e1 = e1 > 0.f ? e1 : 0.2f * e1;
        float w0 = __expf(e0), w1 = __expf(e1);
        wsum += w0 + w1;
#pragma unroll
        for (int q = 0; q < 5; q++) {
            float2 f0 = __bfloat1622float2(*(const __nv_bfloat162*)&ua[q]);
            float2 f1 = __bfloat1622float2(*(const __nv_bfloat162*)&ub[q]);
            acc[q * 2 + 0] = fmaf(w1, f1.x, fmaf(w0, f0.x, acc[q * 2 + 0]));
            acc[q * 2 + 1] = fmaf(w1, f1.y, fmaf(w0, f0.y, acc[q * 2 + 1]));
        }
    }
    if (i < end) {
        int s0 = g_csrc[i];
        float el = g_as2[s0 * 8 + head] + sd;
        el = el > 0.f ? el : 0.2f * el;
        float w0 = __expf(el);
        wsum += w0;
        const uint32_t* p0 = (const uint32_t*)(g_h2b + (size_t)s0 * 320 + lane * 10);
        uint32_t uu[5];
#pragma unroll
        for (int q = 0; q < 5; q++) uu[q] = p0[q];
#pragma unroll
        for (int q = 0; q < 5; q++) {
            float2 f = __bfloat1622float2(*(const __nv_bfloat162*)&uu[q]);
            acc[q * 2 + 0] = fmaf(w0, f.x, acc[q * 2 + 0]);
            acc[q * 2 + 1] = fmaf(w0, f.y, acc[q * 2 + 1]);
        }
    }
    float inv = 1.f / (wsum + 1e-16f);
#pragma unroll
    for (int j = 0; j < 10; j++) acc[j] *= inv;
#pragma unroll
    for (int j = 0; j < 10; j++) {
        acc[j] += __shfl_xor_sync(0xffffffffu, acc[j], 4);
        acc[j] += __shfl_xor_sync(0xffffffffu, acc[j], 8);
        acc[j] += __shfl_xor_sync(0xffffffffu, acc[j], 16);
    }
    int co = (lane & 3) * 10;
    float val[10];
    float vmax = -1e30f;
#pragma unroll
    for (int j = 0; j < 10; j++) {
        val[j] = acc[j] * 0.125f + sb2[co + j];
        vmax = fmaxf(vmax, val[j]);
    }
    vmax = fmaxf(vmax, __shfl_xor_sync(0xffffffffu, vmax, 1));
    vmax = fmaxf(vmax, __shfl_xor_sync(0xffffffffu, vmax, 2));
    float se = 0.f;
#pragma unroll
    for (int j = 0; j < 10; j++) se += __expf(val[j] - vmax);
    se += __shfl_xor_sync(0xffffffffu, se, 1);
    se += __shfl_xor_sync(0xffffffffu, se, 2);
    float lse = vmax + logf(se);
    if (lane < 4) {
        float* op = out + (size_t)gw * 40 + co;
#pragma unroll
        for (int q = 0; q < 5; q++)
            *(float2*)&op[q * 2] = make_float2(val[q * 2] - lse, val[q * 2 + 1] - lse);
    }
}

// ---------------- launcher (forked-stream graph) -----------------
extern "C" void kernel_launch(void* const* d_in, const int* in_sizes, int n_in,
                              void* d_out, int out_size) {
    const float* x   = (const float*)d_in[0];
    const int*   ei  = (const int*)d_in[1];
    // d_in[2] = edge_attr (unused by GATConv)
    const float* W0  = (const float*)d_in[3];
    const float* a0s = (const float*)d_in[4];
    const float* a0d = (const float*)d_in[5];
    const float* b0  = (const float*)d_in[6];
    const float* W2  = (const float*)d_in[7];
    const float* a2s = (const float*)d_in[8];
    const float* a2d = (const float*)d_in[9];
    const float* b2  = (const float*)d_in[10];
    float* out = (float*)d_out;

    static cudaStream_t s2 = nullptr;
    static cudaEvent_t evA = nullptr, evP = nullptr, evB = nullptr, evC = nullptr, evD = nullptr;
    if (!s2) {
        cudaStreamCreateWithFlags(&s2, cudaStreamNonBlocking);
        cudaEventCreateWithFlags(&evA, cudaEventDisableTiming);
        cudaEventCreateWithFlags(&evP, cudaEventDisableTiming);
        cudaEventCreateWithFlags(&evB, cudaEventDisableTiming);
        cudaEventCreateWithFlags(&evC, cudaEventDisableTiming);
        cudaEventCreateWithFlags(&evD, cudaEventDisableTiming);
        cudaFuncSetAttribute(gemm_bf16_nt<0>, cudaFuncAttributeMaxDynamicSharedMemorySize, 65536);
        cudaFuncSetAttribute(gemm_bf16_nt<1>, cudaFuncAttributeMaxDynamicSharedMemorySize, 65536);
    }

    // fork: side stream runs CSR build + logits0; main runs prep/xconv/gemm0
    cudaEventRecord(evA, 0);
    cudaStreamWaitEvent(s2, evA, 0);

    prep_csr_kernel<<<197, 256, 0, s2>>>(ei);
    count_kernel<<<(NTOT + 255) / 256, 256, 0, s2>>>(ei);
    scan1_kernel<<<NB_SCAN, 512, 0, s2>>>();
    scan2_kernel<<<1, 128, 0, s2>>>();
    scan3_kernel<<<NB_SCAN, 512, 0, s2>>>();
    fill_kernel<<<(NTOT + 255) / 256, 256, 0, s2>>>(ei);

    prep_main_kernel<<<594, 256>>>(W0, a0s, a0d, W2, a2s, a2d);
    cudaEventRecord(evP, 0);                 // va0 ready
    cudaStreamWaitEvent(s2, evP, 0);
    logits0_kernel<<<3125, 256, 0, s2>>>(x); // side: as0/ad0 from fp32 x
    cudaEventRecord(evB, s2);

    xconv_kernel<<<12500, 256>>>(x);         // main: x -> bf16
    gemm_bf16_nt<0><<<dim3(391, 4), 256, 65536>>>(NNODE, 512, 256);

    cudaStreamWaitEvent(0, evB, 0);
    pull0_kernel<<<6250, 256>>>(b0);

    // fork: logits2 on s2 while gemm2 runs on main
    cudaEventRecord(evC, 0);
    cudaStreamWaitEvent(s2, evC, 0);
    logits2_kernel<<<3125, 256, 0, s2>>>();
    cudaEventRecord(evD, s2);

    gemm_bf16_nt<1><<<dim3(391, 3), 256, 65536>>>(NNODE, 320, 64);
    cudaStreamWaitEvent(0, evD, 0);
    pull2_kernel<<<6250, 256>>>(b2, out);
}